// round 13
// baseline (speedup 1.0000x reference)
#include <cuda_runtime.h>
#include <cuda_bf16.h>
#include <cstdint>

#define CH    64
#define EPSV  1e-5f
#define MAXN  100000
#define MAXK  27

// ================= scratch (__device__ globals, alloc-free) =================
__device__ float g_buf1[MAXN * CH];      // conv1 raw output (fp32)
__device__ float g_buf2[MAXN * CH];      // conv2 raw output (fp32)
__device__ float g_stats[256];           // [sum1, sumsq1, sum2, sumsq2]
__device__ float g_sb[256];              // [scale1, shift1, scale2, shift2]
__device__ unsigned int g_cnt[2];        // stats completion tickets
// fused hi/lo feature rows: 256B per row = [64 bf16 hi | 64 bf16 lo]
__device__ __align__(16) __nv_bfloat16 g_f[MAXN * 128];
// W pre-packed in fused mma B-fragment order: uint4{bh_reg0, bh_reg1, bl_reg0, bl_reg1}
__device__ __align__(16) uint4 g_Wf1[MAXK * 1024];
__device__ __align__(16) uint4 g_Wf2[MAXK * 1024];

// ================= helpers =================
__device__ __forceinline__ uint32_t smem_u32(const void* p) {
    uint32_t a;
    asm("{ .reg .u64 t; cvta.to.shared.u64 t, %1; cvt.u32.u64 %0, t; }" : "=r"(a) : "l"(p));
    return a;
}

__device__ __forceinline__ void ldmatrix_x4(uint32_t* r, uint32_t addr) {
    asm volatile("ldmatrix.sync.aligned.m8n8.x4.shared.b16 {%0,%1,%2,%3}, [%4];"
                 : "=r"(r[0]), "=r"(r[1]), "=r"(r[2]), "=r"(r[3]) : "r"(addr));
}

__device__ __forceinline__ void mma16816(float* c, const uint32_t* a,
                                         uint32_t b0, uint32_t b1) {
    asm volatile(
        "mma.sync.aligned.m16n8k16.row.col.f32.bf16.bf16.f32 "
        "{%0,%1,%2,%3}, {%4,%5,%6,%7}, {%8,%9}, {%0,%1,%2,%3};"
        : "+f"(c[0]), "+f"(c[1]), "+f"(c[2]), "+f"(c[3])
        : "r"(a[0]), "r"(a[1]), "r"(a[2]), "r"(a[3]), "r"(b0), "r"(b1));
}

__device__ __forceinline__ void cp_async16(uint32_t dst, const void* src, int sz) {
    asm volatile("cp.async.cg.shared.global [%0], [%1], 16, %2;"
                 :: "r"(dst), "l"(src), "r"(sz) : "memory");
}

// SMEM layout for conv kernel (dynamic)
#define OFF_AH   0
#define OFF_AL   16384
#define OFF_B    32768
#define SMEM_BYTES 49152

// ================= kernels =================

// W[k][cin][cout] fp32 -> fused bf16 hi/lo B-fragments, column-permuted for red.v4.
// Also zeroes g_stats + tickets (block 0).
__global__ __launch_bounds__(256)
void prep_w_kernel(const float* __restrict__ W1, const float* __restrict__ W2, int K)
{
    const int k     = blockIdx.x;
    const int layer = blockIdx.y;
    const float* Wk = (layer ? W2 : W1) + (size_t)k * 4096;
    uint4* dst = (layer ? g_Wf2 : g_Wf1) + (size_t)k * 1024;

    if (blockIdx.x == 0 && blockIdx.y == 0) {
        if (threadIdx.x < 64)
            reinterpret_cast<float4*>(g_stats)[threadIdx.x] =
                make_float4(0.f, 0.f, 0.f, 0.f);
        if (threadIdx.x == 64) { g_cnt[0] = 0; g_cnt[1] = 0; }
    }

    for (int q = threadIdx.x; q < 1024; q += 256) {
        const int lane = q & 31;
        const int nt   = (q >> 5) & 7;
        const int ks   = q >> 8;
        const int l    = lane >> 2;
        const int n    = 16 * (nt >> 1) + 4 * (l >> 1) + 2 * (nt & 1) + (l & 1);
        uint32_t r[4];
        #pragma unroll
        for (int reg = 0; reg < 2; ++reg) {
            const int k0   = ks * 16 + (lane & 3) * 2 + reg * 8;
            const float v0 = Wk[k0 * 64 + n];
            const float v1 = Wk[(k0 + 1) * 64 + n];
            const __nv_bfloat16 h0 = __float2bfloat16(v0);
            const __nv_bfloat16 h1 = __float2bfloat16(v1);
            const __nv_bfloat16 l0 = __float2bfloat16(v0 - __bfloat162float(h0));
            const __nv_bfloat16 l1 = __float2bfloat16(v1 - __bfloat162float(h1));
            r[reg]     = (uint32_t)__bfloat16_as_ushort(h0)
                       | ((uint32_t)__bfloat16_as_ushort(h1) << 16);
            r[2 + reg] = (uint32_t)__bfloat16_as_ushort(l0)
                       | ((uint32_t)__bfloat16_as_ushort(l1) << 16);
        }
        dst[q] = make_uint4(r[0], r[1], r[2], r[3]);
    }
}

// fp32 rows -> fused bf16 hi/lo row [64 hi | 64 lo] (optional fused relu(bn)).
// When z1 != nullptr also zero-fills buf rows (fused zero pass).
__global__ __launch_bounds__(256)
void prep_feat_kernel(const float* __restrict__ src, const float* __restrict__ sb,
                      float* __restrict__ z1, float* __restrict__ z2, int N)
{
    const int gid = blockIdx.x * blockDim.x + threadIdx.x;
    if (gid >= N * 8) return;
    const int row = gid >> 3;
    const int c0  = (gid & 7) * 8;

    const float4 v0 = reinterpret_cast<const float4*>(src + (size_t)row * 64 + c0)[0];
    const float4 v1 = reinterpret_cast<const float4*>(src + (size_t)row * 64 + c0)[1];
    float v[8] = {v0.x, v0.y, v0.z, v0.w, v1.x, v1.y, v1.z, v1.w};

    if (sb) {
        #pragma unroll
        for (int j = 0; j < 8; ++j)
            v[j] = fmaxf(fmaf(v[j], sb[c0 + j], sb[64 + c0 + j]), 0.f);
    }

    union { __nv_bfloat16 h[8]; uint4 u; } uh, ul;
    #pragma unroll
    for (int j = 0; j < 8; ++j) {
        const __nv_bfloat16 hi = __float2bfloat16(v[j]);
        uh.h[j] = hi;
        ul.h[j] = __float2bfloat16(v[j] - __bfloat162float(hi));
    }
    // fused row: 16 uint4; hi at [0..7], lo at [8..15]
    reinterpret_cast<uint4*>(g_f)[(size_t)row * 16 + (c0 >> 3)]     = uh.u;
    reinterpret_cast<uint4*>(g_f)[(size_t)row * 16 + 8 + (c0 >> 3)] = ul.u;

    if (z1) {
        const float4 z = make_float4(0.f, 0.f, 0.f, 0.f);
        const size_t f4 = (size_t)row * 16 + (c0 >> 2);
        reinterpret_cast<float4*>(z1)[f4]     = z;
        reinterpret_cast<float4*>(z1)[f4 + 1] = z;
        reinterpret_cast<float4*>(z2)[f4]     = z;
        reinterpret_cast<float4*>(z2)[f4 + 1] = z;
    }
}

// gather (cp.async, issued at entry) -> mma.sync bf16-split -> red.v4 scatter
// 8 warps arranged 4(row)x2(col); each warp: 32 rows x 32 cols. 4 CTAs/SM.
// Gather reads one fused 256B row stream (2 adjacent lines per row).
__global__ __launch_bounds__(256, 4)
void conv_mma_kernel(const __nv_bfloat16* __restrict__ f,
                     const uint4* __restrict__ Wf,
                     const int* __restrict__ in_maps,
                     const int* __restrict__ out_maps,
                     float* __restrict__ out,
                     int M)
{
    extern __shared__ char sm[];
    const int t    = threadIdx.x;
    const int lane = t & 31;
    const int w    = t >> 5;
    const int wr   = w >> 1;      // row group 0..3
    const int wc   = w & 1;       // col group 0..1
    const int k    = blockIdx.y;
    const int m0   = blockIdx.x * 128;
    const int mrem = M - m0;

    const uint32_t ahb = smem_u32(sm + OFF_AH);
    const uint32_t alb = smem_u32(sm + OFF_AL);
    const uint32_t bsb = smem_u32(sm + OFF_B);

    const int* im = in_maps  + (size_t)k * M + m0;
    const int* om = out_maps + (size_t)k * M + m0;

    // A gather via cp.async: 8 lanes per row, one 16B chunk per half (hi+lo).
    {
        const int c = t & 7;          // chunk 0..7
        const int g = t >> 3;         // row sub-index 0..31
        #pragma unroll
        for (int it = 0; it < 4; ++it) {
            const int row = it * 32 + g;
            const int src = (row < mrem) ? im[row] : -1;
            const int sz  = (src >= 0) ? 16 : 0;
            const uint4* base =
                reinterpret_cast<const uint4*>(f) + (uint32_t)(src >= 0 ? src : 0) * 16u;
            const uint32_t d = (uint32_t)(row * 128 + ((c ^ (row & 7)) << 4));
            cp_async16(ahb + d, base + c,     sz);
            cp_async16(alb + d, base + c + 8, sz);
        }
    }
    // B-fragment copy via cp.async (1024 uint4)
    {
        const uint4* s = Wf + (size_t)k * 1024;
        #pragma unroll
        for (int i = 0; i < 4; ++i)
            cp_async16(bsb + (uint32_t)(t + i * 256) * 16u, s + t + i * 256, 16);
    }
    asm volatile("cp.async.commit_group;" ::: "memory");
    asm volatile("cp.async.wait_group 0;" ::: "memory");
    __syncthreads();

    // MMA mainloop: warp covers rows [wr*32, wr*32+32), cols [wc*32, wc*32+32)
    float acc[2][4][4];
    #pragma unroll
    for (int rt = 0; rt < 2; ++rt)
        #pragma unroll
        for (int nl = 0; nl < 4; ++nl)
            #pragma unroll
            for (int j = 0; j < 4; ++j) acc[rt][nl][j] = 0.f;

    const uint4* B = reinterpret_cast<const uint4*>(sm + OFF_B);
    const int half = lane >> 4;

    uint32_t arow[2], sw[2];
    #pragma unroll
    for (int rt = 0; rt < 2; ++rt) {
        const int row = wr * 32 + rt * 16 + (lane & 15);
        arow[rt] = (uint32_t)(row * 128);
        sw[rt]   = (uint32_t)(row & 7);
    }

    #pragma unroll
    for (int ks = 0; ks < 4; ++ks) {
        uint32_t aH[2][4], aL[2][4];
        #pragma unroll
        for (int rt = 0; rt < 2; ++rt) {
            const uint32_t off = arow[rt]
                + ((((uint32_t)(ks * 2 + half)) ^ sw[rt]) << 4);
            ldmatrix_x4(aH[rt], ahb + off);
            ldmatrix_x4(aL[rt], alb + off);
        }
        #pragma unroll
        for (int nl = 0; nl < 4; ++nl) {
            const int nt = wc * 4 + nl;
            const uint4 b = B[(ks * 8 + nt) * 32 + lane];
            #pragma unroll
            for (int rt = 0; rt < 2; ++rt) {
                mma16816(acc[rt][nl], aH[rt], b.x, b.y);
                mma16816(acc[rt][nl], aH[rt], b.z, b.w);
                mma16816(acc[rt][nl], aL[rt], b.x, b.y);
            }
        }
    }

    // scatter via red.v4; out indices by direct LDG, 32-bit offset math
    #pragma unroll
    for (int rt = 0; rt < 2; ++rt) {
        const int r0 = wr * 32 + rt * 16 + (lane >> 2);
        const int o0 = (r0     < mrem) ? om[r0]     : -1;
        const int o1 = (r0 + 8 < mrem) ? om[r0 + 8] : -1;
        const uint32_t cb = 4u * (uint32_t)(lane & 3);
        #pragma unroll
        for (int p = 0; p < 2; ++p) {
            const uint32_t col = 16u * (uint32_t)(wc * 2 + p) + cb;
            if (o0 >= 0) {
                asm volatile("red.global.add.v4.f32 [%0], {%1, %2, %3, %4};"
                    :: "l"(out + (uint32_t)o0 * 64u + col),
                       "f"(acc[rt][2*p][0]), "f"(acc[rt][2*p][1]),
                       "f"(acc[rt][2*p+1][0]), "f"(acc[rt][2*p+1][1]) : "memory");
            }
            if (o1 >= 0) {
                asm volatile("red.global.add.v4.f32 [%0], {%1, %2, %3, %4};"
                    :: "l"(out + (uint32_t)o1 * 64u + col),
                       "f"(acc[rt][2*p][2]), "f"(acc[rt][2*p][3]),
                       "f"(acc[rt][2*p+1][2]), "f"(acc[rt][2*p+1][3]) : "memory");
            }
        }
    }
}

// per-channel sum / sumsq, 8 channels per thread (2x float4), fused finalize
__global__ __launch_bounds__(256)
void stats_kernel(const float* __restrict__ x, int N, float* __restrict__ sums,
                  const float* __restrict__ gamma, const float* __restrict__ beta,
                  float invN, float* __restrict__ sb, int cidx)
{
    const int t  = threadIdx.x;
    const int cg = t & 7;         // channel group (8 channels)
    const int rg = t >> 3;        // 32 row lanes per block
    float s[8] = {0,0,0,0,0,0,0,0};
    float q[8] = {0,0,0,0,0,0,0,0};
    const int stride = gridDim.x * 32;
    for (int r = blockIdx.x * 32 + rg; r < N; r += stride) {
        const float4* p = reinterpret_cast<const float4*>(x + (size_t)r * 64 + cg * 8);
        const float4 v0 = p[0];
        const float4 v1 = p[1];
        s[0] += v0.x; s[1] += v0.y; s[2] += v0.z; s[3] += v0.w;
        s[4] += v1.x; s[5] += v1.y; s[6] += v1.z; s[7] += v1.w;
        q[0] += v0.x * v0.x; q[1] += v0.y * v0.y; q[2] += v0.z * v0.z; q[3] += v0.w * v0.w;
        q[4] += v1.x * v1.x; q[5] += v1.y * v1.y; q[6] += v1.z * v1.z; q[7] += v1.w * v1.w;
    }
    __shared__ float sh[256 * 16];
    __shared__ int last;
    float* my = sh + t * 16;
    #pragma unroll
    for (int j = 0; j < 8; ++j) { my[j] = s[j]; my[8 + j] = q[j]; }
    __syncthreads();
    if (t < 64) {
        const int cgi = t >> 3;   // channel group 0..7
        const int j   = t & 7;    // channel within group
        float S = 0.f, Q = 0.f;
        #pragma unroll
        for (int r = 0; r < 32; ++r) {
            const float* p = sh + (r * 8 + cgi) * 16 + j;
            S += p[0];
            Q += p[8];
        }
        atomicAdd(&sums[t],      S);
        atomicAdd(&sums[64 + t], Q);
    }
    // last block finalizes scale/shift
    __syncthreads();
    if (t == 0) {
        __threadfence();
        last = (atomicAdd(&g_cnt[cidx], 1u) == gridDim.x - 1) ? 1 : 0;
    }
    __syncthreads();
    if (last && t < 64) {
        const float mean = sums[t] * invN;
        const float var  = fmaxf(sums[64 + t] * invN - mean * mean, 0.f);
        const float s2   = gamma[t] * rsqrtf(var + EPSV);
        sb[t]      = s2;
        sb[64 + t] = beta[t] - mean * s2;
    }
}

__global__ __launch_bounds__(256)
void final_kernel(const float* __restrict__ conv2, const float* __restrict__ sb2,
                  const float* __restrict__ feat, float* __restrict__ out, int n4)
{
    int i = blockIdx.x * blockDim.x + threadIdx.x;
    for (int j = i; j < n4; j += gridDim.x * blockDim.x) {
        const float4 v = reinterpret_cast<const float4*>(conv2)[j];
        const float4 f = reinterpret_cast<const float4*>(feat)[j];
        const int c0 = (j & 15) * 4;
        float4 r;
        r.x = fmaxf(fmaf(v.x, sb2[c0 + 0], sb2[64 + c0 + 0]) + f.x, 0.f);
        r.y = fmaxf(fmaf(v.y, sb2[c0 + 1], sb2[64 + c0 + 1]) + f.y, 0.f);
        r.z = fmaxf(fmaf(v.z, sb2[c0 + 2], sb2[64 + c0 + 2]) + f.z, 0.f);
        r.w = fmaxf(fmaf(v.w, sb2[c0 + 3], sb2[64 + c0 + 3]) + f.w, 0.f);
        reinterpret_cast<float4*>(out)[j] = r;
    }
}

// ================= launcher =================
extern "C" void kernel_launch(void* const* d_in, const int* in_sizes, int n_in,
                              void* d_out, int out_size)
{
    const float* features = (const float*)d_in[0];
    const float* W1       = (const float*)d_in[1];
    const float* gamma1   = (const float*)d_in[2];
    const float* beta1    = (const float*)d_in[3];
    const float* W2       = (const float*)d_in[4];
    const float* gamma2   = (const float*)d_in[5];
    const float* beta2    = (const float*)d_in[6];
    const int*   in_maps  = (const int*)d_in[7];
    const int*   out_maps = (const int*)d_in[8];
    float*       out      = (float*)d_out;

    const int N = in_sizes[0] / CH;
    const int K = in_sizes[1] / (CH * CH);
    const int M = in_sizes[7] / K;

    float* buf1;  cudaGetSymbolAddress((void**)&buf1,  g_buf1);
    float* buf2;  cudaGetSymbolAddress((void**)&buf2,  g_buf2);
    float* stats; cudaGetSymbolAddress((void**)&stats, g_stats);
    float* sb;    cudaGetSymbolAddress((void**)&sb,    g_sb);
    __nv_bfloat16* f;
    cudaGetSymbolAddress((void**)&f, g_f);
    uint4 *wf1, *wf2;
    cudaGetSymbolAddress((void**)&wf1, g_Wf1);
    cudaGetSymbolAddress((void**)&wf2, g_Wf2);

    cudaFuncSetAttribute(conv_mma_kernel,
                         cudaFuncAttributeMaxDynamicSharedMemorySize, SMEM_BYTES);

    const int total4 = N * (CH / 4);
    const float invN = 1.0f / (float)N;
    const dim3 convGrid((M + 127) / 128, K);
    const int pfBlocks = (N * 8 + 255) / 256;

    prep_w_kernel<<<dim3(K, 2), 256>>>(W1, W2, K);

    // conv1 (prep also zeroes buf1/buf2)
    prep_feat_kernel<<<pfBlocks, 256>>>(features, nullptr, buf1, buf2, N);
    conv_mma_kernel<<<convGrid, 256, SMEM_BYTES>>>(f, wf1,
                                                   in_maps, out_maps, buf1, M);
    stats_kernel<<<1024, 256>>>(buf1, N, stats, gamma1, beta1, invN, sb, 0);

    // conv2 (BN1+ReLU fused into split pass)
    prep_feat_kernel<<<pfBlocks, 256>>>(buf1, sb, nullptr, nullptr, N);
    conv_mma_kernel<<<convGrid, 256, SMEM_BYTES>>>(f, wf2,
                                                   in_maps, out_maps, buf2, M);
    stats_kernel<<<1024, 256>>>(buf2, N, stats + 128, gamma2, beta2, invN,
                                sb + 128, 1);

    final_kernel<<<1024, 256>>>(buf2, sb + 128, features, out, total4);
}

// round 14
// speedup vs baseline: 1.0596x; 1.0596x over previous
#include <cuda_runtime.h>
#include <cuda_bf16.h>
#include <cstdint>

#define CH    64
#define EPSV  1e-5f
#define MAXN  100000
#define MAXK  27

// ================= scratch (__device__ globals, alloc-free) =================
__device__ float g_buf1[MAXN * CH];      // conv1 raw output (fp32)
__device__ float g_buf2[MAXN * CH];      // conv2 raw output (fp32)
__device__ float g_stats[256];           // [sum1, sumsq1, sum2, sumsq2]
__device__ float g_sb[256];              // [scale1, shift1, scale2, shift2]
__device__ unsigned int g_cnt[2];        // stats completion tickets
// fused hi/lo feature rows: 256B per row = [64 bf16 hi | 64 bf16 lo]
__device__ __align__(16) __nv_bfloat16 g_f[MAXN * 128];
// W pre-packed in fused mma B-fragment order: uint4{bh_reg0, bh_reg1, bl_reg0, bl_reg1}
__device__ __align__(16) uint4 g_Wf1[MAXK * 1024];
__device__ __align__(16) uint4 g_Wf2[MAXK * 1024];

// ================= helpers =================
__device__ __forceinline__ uint32_t smem_u32(const void* p) {
    uint32_t a;
    asm("{ .reg .u64 t; cvta.to.shared.u64 t, %1; cvt.u32.u64 %0, t; }" : "=r"(a) : "l"(p));
    return a;
}

__device__ __forceinline__ void ldmatrix_x4(uint32_t* r, uint32_t addr) {
    asm volatile("ldmatrix.sync.aligned.m8n8.x4.shared.b16 {%0,%1,%2,%3}, [%4];"
                 : "=r"(r[0]), "=r"(r[1]), "=r"(r[2]), "=r"(r[3]) : "r"(addr));
}

__device__ __forceinline__ void mma16816(float* c, const uint32_t* a,
                                         uint32_t b0, uint32_t b1) {
    asm volatile(
        "mma.sync.aligned.m16n8k16.row.col.f32.bf16.bf16.f32 "
        "{%0,%1,%2,%3}, {%4,%5,%6,%7}, {%8,%9}, {%0,%1,%2,%3};"
        : "+f"(c[0]), "+f"(c[1]), "+f"(c[2]), "+f"(c[3])
        : "r"(a[0]), "r"(a[1]), "r"(a[2]), "r"(a[3]), "r"(b0), "r"(b1));
}

__device__ __forceinline__ void cp_async16(uint32_t dst, const void* src, int sz) {
    asm volatile("cp.async.cg.shared.global [%0], [%1], 16, %2;"
                 :: "r"(dst), "l"(src), "r"(sz) : "memory");
}

// SMEM layout for conv kernel (dynamic)
#define OFF_AH   0
#define OFF_AL   16384
#define OFF_B    32768
#define SMEM_BYTES 49152

// ================= kernels =================

// W[k][cin][cout] fp32 -> fused bf16 hi/lo B-fragments, column-permuted for red.v4.
// Also zeroes g_stats + tickets (block 0).
__global__ __launch_bounds__(256)
void prep_w_kernel(const float* __restrict__ W1, const float* __restrict__ W2, int K)
{
    const int k     = blockIdx.x;
    const int layer = blockIdx.y;
    const float* Wk = (layer ? W2 : W1) + (size_t)k * 4096;
    uint4* dst = (layer ? g_Wf2 : g_Wf1) + (size_t)k * 1024;

    if (blockIdx.x == 0 && blockIdx.y == 0) {
        if (threadIdx.x < 64)
            reinterpret_cast<float4*>(g_stats)[threadIdx.x] =
                make_float4(0.f, 0.f, 0.f, 0.f);
        if (threadIdx.x == 64) { g_cnt[0] = 0; g_cnt[1] = 0; }
    }

    for (int q = threadIdx.x; q < 1024; q += 256) {
        const int lane = q & 31;
        const int nt   = (q >> 5) & 7;
        const int ks   = q >> 8;
        const int l    = lane >> 2;
        const int n    = 16 * (nt >> 1) + 4 * (l >> 1) + 2 * (nt & 1) + (l & 1);
        uint32_t r[4];
        #pragma unroll
        for (int reg = 0; reg < 2; ++reg) {
            const int k0   = ks * 16 + (lane & 3) * 2 + reg * 8;
            const float v0 = Wk[k0 * 64 + n];
            const float v1 = Wk[(k0 + 1) * 64 + n];
            const __nv_bfloat16 h0 = __float2bfloat16(v0);
            const __nv_bfloat16 h1 = __float2bfloat16(v1);
            const __nv_bfloat16 l0 = __float2bfloat16(v0 - __bfloat162float(h0));
            const __nv_bfloat16 l1 = __float2bfloat16(v1 - __bfloat162float(h1));
            r[reg]     = (uint32_t)__bfloat16_as_ushort(h0)
                       | ((uint32_t)__bfloat16_as_ushort(h1) << 16);
            r[2 + reg] = (uint32_t)__bfloat16_as_ushort(l0)
                       | ((uint32_t)__bfloat16_as_ushort(l1) << 16);
        }
        dst[q] = make_uint4(r[0], r[1], r[2], r[3]);
    }
}

// fp32 rows -> fused bf16 hi/lo row [64 hi | 64 lo] (optional fused relu(bn)).
// When z1 != nullptr also zero-fills buf rows (fused zero pass).
__global__ __launch_bounds__(256)
void prep_feat_kernel(const float* __restrict__ src, const float* __restrict__ sb,
                      float* __restrict__ z1, float* __restrict__ z2, int N)
{
    const int gid = blockIdx.x * blockDim.x + threadIdx.x;
    if (gid >= N * 8) return;
    const int row = gid >> 3;
    const int c0  = (gid & 7) * 8;

    const float4 v0 = reinterpret_cast<const float4*>(src + (size_t)row * 64 + c0)[0];
    const float4 v1 = reinterpret_cast<const float4*>(src + (size_t)row * 64 + c0)[1];
    float v[8] = {v0.x, v0.y, v0.z, v0.w, v1.x, v1.y, v1.z, v1.w};

    if (sb) {
        #pragma unroll
        for (int j = 0; j < 8; ++j)
            v[j] = fmaxf(fmaf(v[j], sb[c0 + j], sb[64 + c0 + j]), 0.f);
    }

    union { __nv_bfloat16 h[8]; uint4 u; } uh, ul;
    #pragma unroll
    for (int j = 0; j < 8; ++j) {
        const __nv_bfloat16 hi = __float2bfloat16(v[j]);
        uh.h[j] = hi;
        ul.h[j] = __float2bfloat16(v[j] - __bfloat162float(hi));
    }
    // fused row: 16 uint4; hi at [0..7], lo at [8..15]
    reinterpret_cast<uint4*>(g_f)[(size_t)row * 16 + (c0 >> 3)]     = uh.u;
    reinterpret_cast<uint4*>(g_f)[(size_t)row * 16 + 8 + (c0 >> 3)] = ul.u;

    if (z1) {
        const float4 z = make_float4(0.f, 0.f, 0.f, 0.f);
        const size_t f4 = (size_t)row * 16 + (c0 >> 2);
        reinterpret_cast<float4*>(z1)[f4]     = z;
        reinterpret_cast<float4*>(z1)[f4 + 1] = z;
        reinterpret_cast<float4*>(z2)[f4]     = z;
        reinterpret_cast<float4*>(z2)[f4 + 1] = z;
    }
}

// gather (cp.async, issued at entry) -> mma.sync bf16-split -> red.v4 scatter
// 8 warps arranged 4(row)x2(col); each warp: 32 rows x 32 cols. 4 CTAs/SM.
// Gather reads one fused 256B row stream (2 adjacent lines per row).
__global__ __launch_bounds__(256, 4)
void conv_mma_kernel(const __nv_bfloat16* __restrict__ f,
                     const uint4* __restrict__ Wf,
                     const int* __restrict__ in_maps,
                     const int* __restrict__ out_maps,
                     float* __restrict__ out,
                     int M)
{
    extern __shared__ char sm[];
    const int t    = threadIdx.x;
    const int lane = t & 31;
    const int w    = t >> 5;
    const int wr   = w >> 1;      // row group 0..3
    const int wc   = w & 1;       // col group 0..1
    const int k    = blockIdx.y;
    const int m0   = blockIdx.x * 128;
    const int mrem = M - m0;

    const uint32_t ahb = smem_u32(sm + OFF_AH);
    const uint32_t alb = smem_u32(sm + OFF_AL);
    const uint32_t bsb = smem_u32(sm + OFF_B);

    const int* im = in_maps  + (size_t)k * M + m0;
    const int* om = out_maps + (size_t)k * M + m0;

    // A gather via cp.async: 8 lanes per row, one 16B chunk per half (hi+lo).
    {
        const int c = t & 7;          // chunk 0..7
        const int g = t >> 3;         // row sub-index 0..31
        #pragma unroll
        for (int it = 0; it < 4; ++it) {
            const int row = it * 32 + g;
            const int src = (row < mrem) ? im[row] : -1;
            const int sz  = (src >= 0) ? 16 : 0;
            const uint4* base =
                reinterpret_cast<const uint4*>(f) + (uint32_t)(src >= 0 ? src : 0) * 16u;
            const uint32_t d = (uint32_t)(row * 128 + ((c ^ (row & 7)) << 4));
            cp_async16(ahb + d, base + c,     sz);
            cp_async16(alb + d, base + c + 8, sz);
        }
    }
    // B-fragment copy via cp.async (1024 uint4)
    {
        const uint4* s = Wf + (size_t)k * 1024;
        #pragma unroll
        for (int i = 0; i < 4; ++i)
            cp_async16(bsb + (uint32_t)(t + i * 256) * 16u, s + t + i * 256, 16);
    }
    asm volatile("cp.async.commit_group;" ::: "memory");
    asm volatile("cp.async.wait_group 0;" ::: "memory");
    __syncthreads();

    // MMA mainloop: warp covers rows [wr*32, wr*32+32), cols [wc*32, wc*32+32)
    float acc[2][4][4];
    #pragma unroll
    for (int rt = 0; rt < 2; ++rt)
        #pragma unroll
        for (int nl = 0; nl < 4; ++nl)
            #pragma unroll
            for (int j = 0; j < 4; ++j) acc[rt][nl][j] = 0.f;

    const uint4* B = reinterpret_cast<const uint4*>(sm + OFF_B);
    const int half = lane >> 4;

    uint32_t arow[2], sw[2];
    #pragma unroll
    for (int rt = 0; rt < 2; ++rt) {
        const int row = wr * 32 + rt * 16 + (lane & 15);
        arow[rt] = (uint32_t)(row * 128);
        sw[rt]   = (uint32_t)(row & 7);
    }

    #pragma unroll
    for (int ks = 0; ks < 4; ++ks) {
        uint32_t aH[2][4], aL[2][4];
        #pragma unroll
        for (int rt = 0; rt < 2; ++rt) {
            const uint32_t off = arow[rt]
                + ((((uint32_t)(ks * 2 + half)) ^ sw[rt]) << 4);
            ldmatrix_x4(aH[rt], ahb + off);
            ldmatrix_x4(aL[rt], alb + off);
        }
        #pragma unroll
        for (int nl = 0; nl < 4; ++nl) {
            const int nt = wc * 4 + nl;
            const uint4 b = B[(ks * 8 + nt) * 32 + lane];
            #pragma unroll
            for (int rt = 0; rt < 2; ++rt) {
                mma16816(acc[rt][nl], aH[rt], b.x, b.y);
                mma16816(acc[rt][nl], aH[rt], b.z, b.w);
                mma16816(acc[rt][nl], aL[rt], b.x, b.y);
            }
        }
    }

    // scatter via red.v4; out indices by direct LDG, 32-bit offset math
    #pragma unroll
    for (int rt = 0; rt < 2; ++rt) {
        const int r0 = wr * 32 + rt * 16 + (lane >> 2);
        const int o0 = (r0     < mrem) ? om[r0]     : -1;
        const int o1 = (r0 + 8 < mrem) ? om[r0 + 8] : -1;
        const uint32_t cb = 4u * (uint32_t)(lane & 3);
        #pragma unroll
        for (int p = 0; p < 2; ++p) {
            const uint32_t col = 16u * (uint32_t)(wc * 2 + p) + cb;
            if (o0 >= 0) {
                asm volatile("red.global.add.v4.f32 [%0], {%1, %2, %3, %4};"
                    :: "l"(out + (uint32_t)o0 * 64u + col),
                       "f"(acc[rt][2*p][0]), "f"(acc[rt][2*p][1]),
                       "f"(acc[rt][2*p+1][0]), "f"(acc[rt][2*p+1][1]) : "memory");
            }
            if (o1 >= 0) {
                asm volatile("red.global.add.v4.f32 [%0], {%1, %2, %3, %4};"
                    :: "l"(out + (uint32_t)o1 * 64u + col),
                       "f"(acc[rt][2*p][2]), "f"(acc[rt][2*p][3]),
                       "f"(acc[rt][2*p+1][2]), "f"(acc[rt][2*p+1][3]) : "memory");
            }
        }
    }
}

// per-channel sum / sumsq (float4-vectorized, round-12 proven shape),
// fused finalize (last block)
__global__ __launch_bounds__(256)
void stats_kernel(const float* __restrict__ x, int N, float* __restrict__ sums,
                  const float* __restrict__ gamma, const float* __restrict__ beta,
                  float invN, float* __restrict__ sb, int cidx)
{
    const int t  = threadIdx.x;
    const int cg = t & 15;        // channel group (4 channels)
    const int rg = t >> 4;        // 16 row lanes per block
    float s0 = 0.f, s1 = 0.f, s2 = 0.f, s3 = 0.f;
    float q0 = 0.f, q1 = 0.f, q2 = 0.f, q3 = 0.f;
    const int stride = gridDim.x * 16;
    for (int r = blockIdx.x * 16 + rg; r < N; r += stride) {
        const float4 v = reinterpret_cast<const float4*>(x + (size_t)r * 64 + cg * 4)[0];
        s0 += v.x; s1 += v.y; s2 += v.z; s3 += v.w;
        q0 += v.x * v.x; q1 += v.y * v.y; q2 += v.z * v.z; q3 += v.w * v.w;
    }
    __shared__ float sh[256 * 8];
    __shared__ int last;
    float* my = sh + t * 8;
    my[0] = s0; my[1] = s1; my[2] = s2; my[3] = s3;
    my[4] = q0; my[5] = q1; my[6] = q2; my[7] = q3;
    __syncthreads();
    if (t < 64) {
        const int cgi = t >> 2;
        const int j   = t & 3;
        float S = 0.f, Q = 0.f;
        #pragma unroll
        for (int r = 0; r < 16; ++r) {
            const float* p = sh + (r * 16 + cgi) * 8 + j;
            S += p[0];
            Q += p[4];
        }
        atomicAdd(&sums[t],      S);
        atomicAdd(&sums[64 + t], Q);
    }
    // last block finalizes scale/shift
    __syncthreads();
    if (t == 0) {
        __threadfence();
        last = (atomicAdd(&g_cnt[cidx], 1u) == gridDim.x - 1) ? 1 : 0;
    }
    __syncthreads();
    if (last && t < 64) {
        const float mean = sums[t] * invN;
        const float var  = fmaxf(sums[64 + t] * invN - mean * mean, 0.f);
        const float s    = gamma[t] * rsqrtf(var + EPSV);
        sb[t]      = s;
        sb[64 + t] = beta[t] - mean * s;
    }
}

__global__ __launch_bounds__(256)
void final_kernel(const float* __restrict__ conv2, const float* __restrict__ sb2,
                  const float* __restrict__ feat, float* __restrict__ out, int n4)
{
    int i = blockIdx.x * blockDim.x + threadIdx.x;
    for (int j = i; j < n4; j += gridDim.x * blockDim.x) {
        const float4 v = reinterpret_cast<const float4*>(conv2)[j];
        const float4 f = reinterpret_cast<const float4*>(feat)[j];
        const int c0 = (j & 15) * 4;
        float4 r;
        r.x = fmaxf(fmaf(v.x, sb2[c0 + 0], sb2[64 + c0 + 0]) + f.x, 0.f);
        r.y = fmaxf(fmaf(v.y, sb2[c0 + 1], sb2[64 + c0 + 1]) + f.y, 0.f);
        r.z = fmaxf(fmaf(v.z, sb2[c0 + 2], sb2[64 + c0 + 2]) + f.z, 0.f);
        r.w = fmaxf(fmaf(v.w, sb2[c0 + 3], sb2[64 + c0 + 3]) + f.w, 0.f);
        reinterpret_cast<float4*>(out)[j] = r;
    }
}

// ================= launcher =================
extern "C" void kernel_launch(void* const* d_in, const int* in_sizes, int n_in,
                              void* d_out, int out_size)
{
    const float* features = (const float*)d_in[0];
    const float* W1       = (const float*)d_in[1];
    const float* gamma1   = (const float*)d_in[2];
    const float* beta1    = (const float*)d_in[3];
    const float* W2       = (const float*)d_in[4];
    const float* gamma2   = (const float*)d_in[5];
    const float* beta2    = (const float*)d_in[6];
    const int*   in_maps  = (const int*)d_in[7];
    const int*   out_maps = (const int*)d_in[8];
    float*       out      = (float*)d_out;

    const int N = in_sizes[0] / CH;
    const int K = in_sizes[1] / (CH * CH);
    const int M = in_sizes[7] / K;

    float* buf1;  cudaGetSymbolAddress((void**)&buf1,  g_buf1);
    float* buf2;  cudaGetSymbolAddress((void**)&buf2,  g_buf2);
    float* stats; cudaGetSymbolAddress((void**)&stats, g_stats);
    float* sb;    cudaGetSymbolAddress((void**)&sb,    g_sb);
    __nv_bfloat16* f;
    cudaGetSymbolAddress((void**)&f, g_f);
    uint4 *wf1, *wf2;
    cudaGetSymbolAddress((void**)&wf1, g_Wf1);
    cudaGetSymbolAddress((void**)&wf2, g_Wf2);

    cudaFuncSetAttribute(conv_mma_kernel,
                         cudaFuncAttributeMaxDynamicSharedMemorySize, SMEM_BYTES);

    const int total4 = N * (CH / 4);
    const float invN = 1.0f / (float)N;
    const dim3 convGrid((M + 127) / 128, K);
    const int pfBlocks = (N * 8 + 255) / 256;

    prep_w_kernel<<<dim3(K, 2), 256>>>(W1, W2, K);

    // conv1 (prep also zeroes buf1/buf2)
    prep_feat_kernel<<<pfBlocks, 256>>>(features, nullptr, buf1, buf2, N);
    conv_mma_kernel<<<convGrid, 256, SMEM_BYTES>>>(f, wf1,
                                                   in_maps, out_maps, buf1, M);
    stats_kernel<<<512, 256>>>(buf1, N, stats, gamma1, beta1, invN, sb, 0);

    // conv2 (BN1+ReLU fused into split pass)
    prep_feat_kernel<<<pfBlocks, 256>>>(buf1, sb, nullptr, nullptr, N);
    conv_mma_kernel<<<convGrid, 256, SMEM_BYTES>>>(f, wf2,
                                                   in_maps, out_maps, buf2, M);
    stats_kernel<<<512, 256>>>(buf2, N, stats + 128, gamma2, beta2, invN,
                               sb + 128, 1);

    final_kernel<<<1024, 256>>>(buf2, sb + 128, features, out, total4);
}

// round 15
// speedup vs baseline: 1.1906x; 1.1237x over previous
#include <cuda_runtime.h>
#include <cuda_fp16.h>
#include <cstdint>

#define CH    64
#define EPSV  1e-5f
#define WSC   1024.0f
#define WSC2  1048576.0f
#define MAXN  100000
#define MAXK  27

// ================= scratch (__device__ globals, alloc-free) =================
__device__ float g_buf1[MAXN * CH];      // conv1 raw output (fp32, W-scaled)
__device__ float g_buf2[MAXN * CH];      // conv2 raw output (fp32, W-scaled)
__device__ float g_stats[256];           // [sum1, sumsq1, sum2, sumsq2]
__device__ float g_sb[256];              // [scale1, shift1, scale2, shift2]
__device__ unsigned int g_cnt[2];        // stats completion tickets
// fp16 feature rows: 128B per row (64 half)
__device__ __align__(16) __half g_f[MAXN * CH];
// W*1024 fp16 hi/lo in fused mma B-fragment order: uint4{bh0, bh1, bl0, bl1}
__device__ __align__(16) uint4 g_Wf1[MAXK * 1024];
__device__ __align__(16) uint4 g_Wf2[MAXK * 1024];

// ================= helpers =================
__device__ __forceinline__ uint32_t smem_u32(const void* p) {
    uint32_t a;
    asm("{ .reg .u64 t; cvta.to.shared.u64 t, %1; cvt.u32.u64 %0, t; }" : "=r"(a) : "l"(p));
    return a;
}

__device__ __forceinline__ void ldmatrix_x4(uint32_t* r, uint32_t addr) {
    asm volatile("ldmatrix.sync.aligned.m8n8.x4.shared.b16 {%0,%1,%2,%3}, [%4];"
                 : "=r"(r[0]), "=r"(r[1]), "=r"(r[2]), "=r"(r[3]) : "r"(addr));
}

__device__ __forceinline__ void mma16816(float* c, const uint32_t* a,
                                         uint32_t b0, uint32_t b1) {
    asm volatile(
        "mma.sync.aligned.m16n8k16.row.col.f32.f16.f16.f32 "
        "{%0,%1,%2,%3}, {%4,%5,%6,%7}, {%8,%9}, {%0,%1,%2,%3};"
        : "+f"(c[0]), "+f"(c[1]), "+f"(c[2]), "+f"(c[3])
        : "r"(a[0]), "r"(a[1]), "r"(a[2]), "r"(a[3]), "r"(b0), "r"(b1));
}

__device__ __forceinline__ void cp_async16(uint32_t dst, const void* src, int sz) {
    asm volatile("cp.async.cg.shared.global [%0], [%1], 16, %2;"
                 :: "r"(dst), "l"(src), "r"(sz) : "memory");
}

// SMEM layout for conv kernel (dynamic)
#define OFF_A    0
#define OFF_B    16384
#define SMEM_BYTES 32768

// ================= kernels =================

// W[k][cin][cout] fp32 -> (W*1024) fp16 hi/lo B-fragments, column-permuted.
// Also zeroes g_stats + tickets (block 0).
__global__ __launch_bounds__(256)
void prep_w_kernel(const float* __restrict__ W1, const float* __restrict__ W2, int K)
{
    const int k     = blockIdx.x;
    const int layer = blockIdx.y;
    const float* Wk = (layer ? W2 : W1) + (size_t)k * 4096;
    uint4* dst = (layer ? g_Wf2 : g_Wf1) + (size_t)k * 1024;

    if (blockIdx.x == 0 && blockIdx.y == 0) {
        if (threadIdx.x < 64)
            reinterpret_cast<float4*>(g_stats)[threadIdx.x] =
                make_float4(0.f, 0.f, 0.f, 0.f);
        if (threadIdx.x == 64) { g_cnt[0] = 0; g_cnt[1] = 0; }
    }

    for (int q = threadIdx.x; q < 1024; q += 256) {
        const int lane = q & 31;
        const int nt   = (q >> 5) & 7;
        const int ks   = q >> 8;
        const int l    = lane >> 2;
        const int n    = 16 * (nt >> 1) + 4 * (l >> 1) + 2 * (nt & 1) + (l & 1);
        uint32_t r[4];
        #pragma unroll
        for (int reg = 0; reg < 2; ++reg) {
            const int k0   = ks * 16 + (lane & 3) * 2 + reg * 8;
            const float v0 = Wk[k0 * 64 + n] * WSC;
            const float v1 = Wk[(k0 + 1) * 64 + n] * WSC;
            const __half h0 = __float2half(v0);
            const __half h1 = __float2half(v1);
            const __half l0 = __float2half(v0 - __half2float(h0));
            const __half l1 = __float2half(v1 - __half2float(h1));
            r[reg]     = (uint32_t)__half_as_ushort(h0)
                       | ((uint32_t)__half_as_ushort(h1) << 16);
            r[2 + reg] = (uint32_t)__half_as_ushort(l0)
                       | ((uint32_t)__half_as_ushort(l1) << 16);
        }
        dst[q] = make_uint4(r[0], r[1], r[2], r[3]);
    }
}

// fp32 rows -> fp16 rows (optional fused relu(bn) via sb).
// When z1 != nullptr also zero-fills buf rows (fused zero pass).
__global__ __launch_bounds__(256)
void prep_feat_kernel(const float* __restrict__ src, const float* __restrict__ sb,
                      float* __restrict__ z1, float* __restrict__ z2, int N)
{
    const int gid = blockIdx.x * blockDim.x + threadIdx.x;
    if (gid >= N * 8) return;
    const int row = gid >> 3;
    const int c0  = (gid & 7) * 8;

    const float4 v0 = reinterpret_cast<const float4*>(src + (size_t)row * 64 + c0)[0];
    const float4 v1 = reinterpret_cast<const float4*>(src + (size_t)row * 64 + c0)[1];
    float v[8] = {v0.x, v0.y, v0.z, v0.w, v1.x, v1.y, v1.z, v1.w};

    if (sb) {
        #pragma unroll
        for (int j = 0; j < 8; ++j)
            v[j] = fmaxf(fmaf(v[j], sb[c0 + j], sb[64 + c0 + j]), 0.f);
    }

    union { __half h[8]; uint4 u; } uh;
    #pragma unroll
    for (int j = 0; j < 8; ++j) uh.h[j] = __float2half(v[j]);
    reinterpret_cast<uint4*>(g_f)[(size_t)row * 8 + (c0 >> 3)] = uh.u;

    if (z1) {
        const float4 z = make_float4(0.f, 0.f, 0.f, 0.f);
        const size_t f4 = (size_t)row * 16 + (c0 >> 2);
        reinterpret_cast<float4*>(z1)[f4]     = z;
        reinterpret_cast<float4*>(z1)[f4 + 1] = z;
        reinterpret_cast<float4*>(z2)[f4]     = z;
        reinterpret_cast<float4*>(z2)[f4 + 1] = z;
    }
}

// gather (cp.async) -> mma.sync fp16 asymmetric split -> red.v4 scatter
// 8 warps arranged 4(row)x2(col); each warp: 32 rows x 32 cols. 4 CTAs/SM.
// A single fp16 (128B/row); W split hi/lo -> 2 MMAs per b fragment (64/warp).
__global__ __launch_bounds__(256, 4)
void conv_mma_kernel(const __half* __restrict__ f,
                     const uint4* __restrict__ Wf,
                     const int* __restrict__ in_maps,
                     const int* __restrict__ out_maps,
                     float* __restrict__ out,
                     int M)
{
    extern __shared__ char sm[];
    const int t    = threadIdx.x;
    const int lane = t & 31;
    const int w    = t >> 5;
    const int wr   = w >> 1;      // row group 0..3
    const int wc   = w & 1;       // col group 0..1
    const int k    = blockIdx.y;
    const int m0   = blockIdx.x * 128;
    const int mrem = M - m0;

    const uint32_t ab  = smem_u32(sm + OFF_A);
    const uint32_t bsb = smem_u32(sm + OFF_B);

    const int* im = in_maps  + (size_t)k * M + m0;
    const int* om = out_maps + (size_t)k * M + m0;

    // A gather via cp.async: 8 lanes per row, one 16B chunk each.
    {
        const int c = t & 7;          // chunk 0..7
        const int g = t >> 3;         // row sub-index 0..31
        #pragma unroll
        for (int it = 0; it < 4; ++it) {
            const int row = it * 32 + g;
            const int src = (row < mrem) ? im[row] : -1;
            const int sz  = (src >= 0) ? 16 : 0;
            const uint4* base =
                reinterpret_cast<const uint4*>(f) + (uint32_t)(src >= 0 ? src : 0) * 8u;
            const uint32_t d = (uint32_t)(row * 128 + ((c ^ (row & 7)) << 4));
            cp_async16(ab + d, base + c, sz);
        }
    }
    // B-fragment copy via cp.async (1024 uint4)
    {
        const uint4* s = Wf + (size_t)k * 1024;
        #pragma unroll
        for (int i = 0; i < 4; ++i)
            cp_async16(bsb + (uint32_t)(t + i * 256) * 16u, s + t + i * 256, 16);
    }
    asm volatile("cp.async.commit_group;" ::: "memory");
    asm volatile("cp.async.wait_group 0;" ::: "memory");
    __syncthreads();

    // MMA mainloop: warp covers rows [wr*32, wr*32+32), cols [wc*32, wc*32+32)
    float acc[2][4][4];
    #pragma unroll
    for (int rt = 0; rt < 2; ++rt)
        #pragma unroll
        for (int nl = 0; nl < 4; ++nl)
            #pragma unroll
            for (int j = 0; j < 4; ++j) acc[rt][nl][j] = 0.f;

    const uint4* B = reinterpret_cast<const uint4*>(sm + OFF_B);
    const int half = lane >> 4;

    uint32_t arow[2], sw[2];
    #pragma unroll
    for (int rt = 0; rt < 2; ++rt) {
        const int row = wr * 32 + rt * 16 + (lane & 15);
        arow[rt] = (uint32_t)(row * 128);
        sw[rt]   = (uint32_t)(row & 7);
    }

    #pragma unroll
    for (int ks = 0; ks < 4; ++ks) {
        uint32_t aH[2][4];
        #pragma unroll
        for (int rt = 0; rt < 2; ++rt) {
            const uint32_t off = arow[rt]
                + ((((uint32_t)(ks * 2 + half)) ^ sw[rt]) << 4);
            ldmatrix_x4(aH[rt], ab + off);
        }
        #pragma unroll
        for (int nl = 0; nl < 4; ++nl) {
            const int nt = wc * 4 + nl;
            const uint4 b = B[(ks * 8 + nt) * 32 + lane];
            #pragma unroll
            for (int rt = 0; rt < 2; ++rt) {
                mma16816(acc[rt][nl], aH[rt], b.x, b.y);
                mma16816(acc[rt][nl], aH[rt], b.z, b.w);
            }
        }
    }

    // scatter via red.v4; out indices by direct LDG, 32-bit offset math
    #pragma unroll
    for (int rt = 0; rt < 2; ++rt) {
        const int r0 = wr * 32 + rt * 16 + (lane >> 2);
        const int o0 = (r0     < mrem) ? om[r0]     : -1;
        const int o1 = (r0 + 8 < mrem) ? om[r0 + 8] : -1;
        const uint32_t cb = 4u * (uint32_t)(lane & 3);
        #pragma unroll
        for (int p = 0; p < 2; ++p) {
            const uint32_t col = 16u * (uint32_t)(wc * 2 + p) + cb;
            if (o0 >= 0) {
                asm volatile("red.global.add.v4.f32 [%0], {%1, %2, %3, %4};"
                    :: "l"(out + (uint32_t)o0 * 64u + col),
                       "f"(acc[rt][2*p][0]), "f"(acc[rt][2*p][1]),
                       "f"(acc[rt][2*p+1][0]), "f"(acc[rt][2*p+1][1]) : "memory");
            }
            if (o1 >= 0) {
                asm volatile("red.global.add.v4.f32 [%0], {%1, %2, %3, %4};"
                    :: "l"(out + (uint32_t)o1 * 64u + col),
                       "f"(acc[rt][2*p][2]), "f"(acc[rt][2*p][3]),
                       "f"(acc[rt][2*p+1][2]), "f"(acc[rt][2*p+1][3]) : "memory");
            }
        }
    }
}

// per-channel sum / sumsq (float4, proven 16-lane layout, 2 rows per iter),
// fused finalize (last block). Data is W-scaled; EPS compensated by WSC2.
__global__ __launch_bounds__(256)
void stats_kernel(const float* __restrict__ x, int N, float* __restrict__ sums,
                  const float* __restrict__ gamma, const float* __restrict__ beta,
                  float invN, float* __restrict__ sb, int cidx)
{
    const int t  = threadIdx.x;
    const int cg = t & 15;        // channel group (4 channels)
    const int rg = t >> 4;        // 16 row lanes per block
    float s0 = 0.f, s1 = 0.f, s2 = 0.f, s3 = 0.f;
    float q0 = 0.f, q1 = 0.f, q2 = 0.f, q3 = 0.f;
    const int stride = gridDim.x * 32;
    for (int r = blockIdx.x * 32 + rg; r < N; r += stride) {
        const float4 v = reinterpret_cast<const float4*>(x + (size_t)r * 64 + cg * 4)[0];
        s0 += v.x; s1 += v.y; s2 += v.z; s3 += v.w;
        q0 += v.x * v.x; q1 += v.y * v.y; q2 += v.z * v.z; q3 += v.w * v.w;
        const int r2 = r + 16;
        if (r2 < N) {
            const float4 u = reinterpret_cast<const float4*>(x + (size_t)r2 * 64 + cg * 4)[0];
            s0 += u.x; s1 += u.y; s2 += u.z; s3 += u.w;
            q0 += u.x * u.x; q1 += u.y * u.y; q2 += u.z * u.z; q3 += u.w * u.w;
        }
    }
    __shared__ float sh[256 * 8];
    __shared__ int last;
    float* my = sh + t * 8;
    my[0] = s0; my[1] = s1; my[2] = s2; my[3] = s3;
    my[4] = q0; my[5] = q1; my[6] = q2; my[7] = q3;
    __syncthreads();
    if (t < 64) {
        const int cgi = t >> 2;
        const int j   = t & 3;
        float S = 0.f, Q = 0.f;
        #pragma unroll
        for (int r = 0; r < 16; ++r) {
            const float* p = sh + (r * 16 + cgi) * 8 + j;
            S += p[0];
            Q += p[4];
        }
        atomicAdd(&sums[t],      S);
        atomicAdd(&sums[64 + t], Q);
    }
    // last block finalizes scale/shift
    __syncthreads();
    if (t == 0) {
        __threadfence();
        last = (atomicAdd(&g_cnt[cidx], 1u) == gridDim.x - 1) ? 1 : 0;
    }
    __syncthreads();
    if (last && t < 64) {
        const float mean = sums[t] * invN;
        const float var  = fmaxf(sums[64 + t] * invN - mean * mean, 0.f);
        const float s    = gamma[t] * rsqrtf(var + EPSV * WSC2);
        sb[t]      = s;
        sb[64 + t] = beta[t] - mean * s;
    }
}

__global__ __launch_bounds__(256)
void final_kernel(const float* __restrict__ conv2, const float* __restrict__ sb2,
                  const float* __restrict__ feat, float* __restrict__ out, int n4)
{
    int i = blockIdx.x * blockDim.x + threadIdx.x;
    for (int j = i; j < n4; j += gridDim.x * blockDim.x) {
        const float4 v = reinterpret_cast<const float4*>(conv2)[j];
        const float4 f = reinterpret_cast<const float4*>(feat)[j];
        const int c0 = (j & 15) * 4;
        float4 r;
        r.x = fmaxf(fmaf(v.x, sb2[c0 + 0], sb2[64 + c0 + 0]) + f.x, 0.f);
        r.y = fmaxf(fmaf(v.y, sb2[c0 + 1], sb2[64 + c0 + 1]) + f.y, 0.f);
        r.z = fmaxf(fmaf(v.z, sb2[c0 + 2], sb2[64 + c0 + 2]) + f.z, 0.f);
        r.w = fmaxf(fmaf(v.w, sb2[c0 + 3], sb2[64 + c0 + 3]) + f.w, 0.f);
        reinterpret_cast<float4*>(out)[j] = r;
    }
}

// ================= launcher =================
extern "C" void kernel_launch(void* const* d_in, const int* in_sizes, int n_in,
                              void* d_out, int out_size)
{
    const float* features = (const float*)d_in[0];
    const float* W1       = (const float*)d_in[1];
    const float* gamma1   = (const float*)d_in[2];
    const float* beta1    = (const float*)d_in[3];
    const float* W2       = (const float*)d_in[4];
    const float* gamma2   = (const float*)d_in[5];
    const float* beta2    = (const float*)d_in[6];
    const int*   in_maps  = (const int*)d_in[7];
    const int*   out_maps = (const int*)d_in[8];
    float*       out      = (float*)d_out;

    const int N = in_sizes[0] / CH;
    const int K = in_sizes[1] / (CH * CH);
    const int M = in_sizes[7] / K;

    float* buf1;  cudaGetSymbolAddress((void**)&buf1,  g_buf1);
    float* buf2;  cudaGetSymbolAddress((void**)&buf2,  g_buf2);
    float* stats; cudaGetSymbolAddress((void**)&stats, g_stats);
    float* sb;    cudaGetSymbolAddress((void**)&sb,    g_sb);
    __half* f;
    cudaGetSymbolAddress((void**)&f, g_f);
    uint4 *wf1, *wf2;
    cudaGetSymbolAddress((void**)&wf1, g_Wf1);
    cudaGetSymbolAddress((void**)&wf2, g_Wf2);

    cudaFuncSetAttribute(conv_mma_kernel,
                         cudaFuncAttributeMaxDynamicSharedMemorySize, SMEM_BYTES);

    const int total4 = N * (CH / 4);
    const float invN = 1.0f / (float)N;
    const dim3 convGrid((M + 127) / 128, K);
    const int pfBlocks = (N * 8 + 255) / 256;

    prep_w_kernel<<<dim3(K, 2), 256>>>(W1, W2, K);

    // conv1 (prep also zeroes buf1/buf2)
    prep_feat_kernel<<<pfBlocks, 256>>>(features, nullptr, buf1, buf2, N);
    conv_mma_kernel<<<convGrid, 256, SMEM_BYTES>>>(f, wf1,
                                                   in_maps, out_maps, buf1, M);
    stats_kernel<<<512, 256>>>(buf1, N, stats, gamma1, beta1, invN, sb, 0);

    // conv2 (BN1+ReLU fused into fp16 convert)
    prep_feat_kernel<<<pfBlocks, 256>>>(buf1, sb, nullptr, nullptr, N);
    conv_mma_kernel<<<convGrid, 256, SMEM_BYTES>>>(f, wf2,
                                                   in_maps, out_maps, buf2, M);
    stats_kernel<<<512, 256>>>(buf2, N, stats + 128, gamma2, beta2, invN,
                               sb + 128, 1);

    final_kernel<<<1024, 256>>>(buf2, sb + 128, features, out, total4);
}

// round 16
// speedup vs baseline: 1.2382x; 1.0399x over previous
#include <cuda_runtime.h>
#include <cuda_fp16.h>
#include <cstdint>

#define CH    64
#define EPSV  1e-5f
#define WSC   1024.0f
#define WSC2  1048576.0f
#define MAXN  100000
#define MAXK  27

// ================= scratch (__device__ globals, alloc-free) =================
__device__ float g_buf1[MAXN * CH];      // conv1 raw output (fp32, W-scaled)
__device__ float g_buf2[MAXN * CH];      // conv2 raw output (fp32, W-scaled)
__device__ float g_stats[256];           // [sum1, sumsq1, sum2, sumsq2]
__device__ float g_sb[256];              // [scale1, shift1, scale2, shift2]
__device__ unsigned int g_cnt[2];        // stats completion tickets
// fp16 feature rows: 128B per row (64 half)
__device__ __align__(16) __half g_f[MAXN * CH];
// W*1024 single fp16 in mma B-fragment order: uint2{b_reg0, b_reg1} per (ks,nt,lane)
__device__ __align__(16) uint2 g_Wf1[MAXK * 1024];
__device__ __align__(16) uint2 g_Wf2[MAXK * 1024];

// ================= helpers =================
__device__ __forceinline__ uint32_t smem_u32(const void* p) {
    uint32_t a;
    asm("{ .reg .u64 t; cvta.to.shared.u64 t, %1; cvt.u32.u64 %0, t; }" : "=r"(a) : "l"(p));
    return a;
}

__device__ __forceinline__ void ldmatrix_x4(uint32_t* r, uint32_t addr) {
    asm volatile("ldmatrix.sync.aligned.m8n8.x4.shared.b16 {%0,%1,%2,%3}, [%4];"
                 : "=r"(r[0]), "=r"(r[1]), "=r"(r[2]), "=r"(r[3]) : "r"(addr));
}

__device__ __forceinline__ void mma16816(float* c, const uint32_t* a,
                                         uint32_t b0, uint32_t b1) {
    asm volatile(
        "mma.sync.aligned.m16n8k16.row.col.f32.f16.f16.f32 "
        "{%0,%1,%2,%3}, {%4,%5,%6,%7}, {%8,%9}, {%0,%1,%2,%3};"
        : "+f"(c[0]), "+f"(c[1]), "+f"(c[2]), "+f"(c[3])
        : "r"(a[0]), "r"(a[1]), "r"(a[2]), "r"(a[3]), "r"(b0), "r"(b1));
}

__device__ __forceinline__ void cp_async16(uint32_t dst, const void* src, int sz) {
    asm volatile("cp.async.cg.shared.global [%0], [%1], 16, %2;"
                 :: "r"(dst), "l"(src), "r"(sz) : "memory");
}

// SMEM layout for conv kernel (dynamic)
#define OFF_A    0
#define OFF_B    16384
#define SMEM_BYTES 24576

// ================= kernels =================

// W[k][cin][cout] fp32 -> (W*1024) fp16 B-fragments, column-permuted for red.v4.
// Also zeroes g_stats + tickets (block 0).
__global__ __launch_bounds__(256)
void prep_w_kernel(const float* __restrict__ W1, const float* __restrict__ W2, int K)
{
    const int k     = blockIdx.x;
    const int layer = blockIdx.y;
    const float* Wk = (layer ? W2 : W1) + (size_t)k * 4096;
    uint2* dst = (layer ? g_Wf2 : g_Wf1) + (size_t)k * 1024;

    if (blockIdx.x == 0 && blockIdx.y == 0) {
        if (threadIdx.x < 64)
            reinterpret_cast<float4*>(g_stats)[threadIdx.x] =
                make_float4(0.f, 0.f, 0.f, 0.f);
        if (threadIdx.x == 64) { g_cnt[0] = 0; g_cnt[1] = 0; }
    }

    for (int q = threadIdx.x; q < 1024; q += 256) {
        const int lane = q & 31;
        const int nt   = (q >> 5) & 7;
        const int ks   = q >> 8;
        const int l    = lane >> 2;
        const int n    = 16 * (nt >> 1) + 4 * (l >> 1) + 2 * (nt & 1) + (l & 1);
        uint32_t r[2];
        #pragma unroll
        for (int reg = 0; reg < 2; ++reg) {
            const int k0   = ks * 16 + (lane & 3) * 2 + reg * 8;
            const __half h0 = __float2half(Wk[k0 * 64 + n] * WSC);
            const __half h1 = __float2half(Wk[(k0 + 1) * 64 + n] * WSC);
            r[reg] = (uint32_t)__half_as_ushort(h0)
                   | ((uint32_t)__half_as_ushort(h1) << 16);
        }
        dst[q] = make_uint2(r[0], r[1]);
    }
}

// fp32 rows -> fp16 rows (optional fused relu(bn) via sb).
// When z1 != nullptr also zero-fills buf rows (fused zero pass).
__global__ __launch_bounds__(256)
void prep_feat_kernel(const float* __restrict__ src, const float* __restrict__ sb,
                      float* __restrict__ z1, float* __restrict__ z2, int N)
{
    const int gid = blockIdx.x * blockDim.x + threadIdx.x;
    if (gid >= N * 8) return;
    const int row = gid >> 3;
    const int c0  = (gid & 7) * 8;

    const float4 v0 = reinterpret_cast<const float4*>(src + (size_t)row * 64 + c0)[0];
    const float4 v1 = reinterpret_cast<const float4*>(src + (size_t)row * 64 + c0)[1];
    float v[8] = {v0.x, v0.y, v0.z, v0.w, v1.x, v1.y, v1.z, v1.w};

    if (sb) {
        #pragma unroll
        for (int j = 0; j < 8; ++j)
            v[j] = fmaxf(fmaf(v[j], sb[c0 + j], sb[64 + c0 + j]), 0.f);
    }

    union { __half h[8]; uint4 u; } uh;
    #pragma unroll
    for (int j = 0; j < 8; ++j) uh.h[j] = __float2half(v[j]);
    reinterpret_cast<uint4*>(g_f)[(size_t)row * 8 + (c0 >> 3)] = uh.u;

    if (z1) {
        const float4 z = make_float4(0.f, 0.f, 0.f, 0.f);
        const size_t f4 = (size_t)row * 16 + (c0 >> 2);
        reinterpret_cast<float4*>(z1)[f4]     = z;
        reinterpret_cast<float4*>(z1)[f4 + 1] = z;
        reinterpret_cast<float4*>(z2)[f4]     = z;
        reinterpret_cast<float4*>(z2)[f4 + 1] = z;
    }
}

// gather (cp.async) -> mma.sync fp16 -> red.v4 scatter
// 8 warps arranged 4(row)x2(col); each warp: 32 rows x 32 cols. 4 CTAs/SM.
// Single fp16 A and W: 32 MMAs/warp, B fragments 8KB.
__global__ __launch_bounds__(256, 4)
void conv_mma_kernel(const __half* __restrict__ f,
                     const uint2* __restrict__ Wf,
                     const int* __restrict__ in_maps,
                     const int* __restrict__ out_maps,
                     float* __restrict__ out,
                     int M)
{
    extern __shared__ char sm[];
    const int t    = threadIdx.x;
    const int lane = t & 31;
    const int w    = t >> 5;
    const int wr   = w >> 1;      // row group 0..3
    const int wc   = w & 1;       // col group 0..1
    const int k    = blockIdx.y;
    const int m0   = blockIdx.x * 128;
    const int mrem = M - m0;

    const uint32_t ab  = smem_u32(sm + OFF_A);
    const uint32_t bsb = smem_u32(sm + OFF_B);

    const int* im = in_maps  + (size_t)k * M + m0;
    const int* om = out_maps + (size_t)k * M + m0;

    // A gather via cp.async: 8 lanes per row, one 16B chunk each.
    {
        const int c = t & 7;          // chunk 0..7
        const int g = t >> 3;         // row sub-index 0..31
        #pragma unroll
        for (int it = 0; it < 4; ++it) {
            const int row = it * 32 + g;
            const int src = (row < mrem) ? im[row] : -1;
            const int sz  = (src >= 0) ? 16 : 0;
            const uint4* base =
                reinterpret_cast<const uint4*>(f) + (uint32_t)(src >= 0 ? src : 0) * 8u;
            const uint32_t d = (uint32_t)(row * 128 + ((c ^ (row & 7)) << 4));
            cp_async16(ab + d, base + c, sz);
        }
    }
    // B-fragment copy via cp.async (512 uint4 = 8KB)
    {
        const uint4* s = reinterpret_cast<const uint4*>(Wf + (size_t)k * 1024);
        cp_async16(bsb + (uint32_t)t * 16u,         s + t,       16);
        cp_async16(bsb + (uint32_t)(t + 256) * 16u, s + t + 256, 16);
    }
    asm volatile("cp.async.commit_group;" ::: "memory");
    asm volatile("cp.async.wait_group 0;" ::: "memory");
    __syncthreads();

    // MMA mainloop: warp covers rows [wr*32, wr*32+32), cols [wc*32, wc*32+32)
    float acc[2][4][4];
    #pragma unroll
    for (int rt = 0; rt < 2; ++rt)
        #pragma unroll
        for (int nl = 0; nl < 4; ++nl)
            #pragma unroll
            for (int j = 0; j < 4; ++j) acc[rt][nl][j] = 0.f;

    const uint2* B = reinterpret_cast<const uint2*>(sm + OFF_B);
    const int half = lane >> 4;

    uint32_t arow[2], sw[2];
    #pragma unroll
    for (int rt = 0; rt < 2; ++rt) {
        const int row = wr * 32 + rt * 16 + (lane & 15);
        arow[rt] = (uint32_t)(row * 128);
        sw[rt]   = (uint32_t)(row & 7);
    }

    #pragma unroll
    for (int ks = 0; ks < 4; ++ks) {
        uint32_t aH[2][4];
        #pragma unroll
        for (int rt = 0; rt < 2; ++rt) {
            const uint32_t off = arow[rt]
                + ((((uint32_t)(ks * 2 + half)) ^ sw[rt]) << 4);
            ldmatrix_x4(aH[rt], ab + off);
        }
        #pragma unroll
        for (int nl = 0; nl < 4; ++nl) {
            const int nt = wc * 4 + nl;
            const uint2 b = B[(ks * 8 + nt) * 32 + lane];
            #pragma unroll
            for (int rt = 0; rt < 2; ++rt)
                mma16816(acc[rt][nl], aH[rt], b.x, b.y);
        }
    }

    // scatter via red.v4; out indices by direct LDG, 32-bit offset math
    #pragma unroll
    for (int rt = 0; rt < 2; ++rt) {
        const int r0 = wr * 32 + rt * 16 + (lane >> 2);
        const int o0 = (r0     < mrem) ? om[r0]     : -1;
        const int o1 = (r0 + 8 < mrem) ? om[r0 + 8] : -1;
        const uint32_t cb = 4u * (uint32_t)(lane & 3);
        #pragma unroll
        for (int p = 0; p < 2; ++p) {
            const uint32_t col = 16u * (uint32_t)(wc * 2 + p) + cb;
            if (o0 >= 0) {
                asm volatile("red.global.add.v4.f32 [%0], {%1, %2, %3, %4};"
                    :: "l"(out + (uint32_t)o0 * 64u + col),
                       "f"(acc[rt][2*p][0]), "f"(acc[rt][2*p][1]),
                       "f"(acc[rt][2*p+1][0]), "f"(acc[rt][2*p+1][1]) : "memory");
            }
            if (o1 >= 0) {
                asm volatile("red.global.add.v4.f32 [%0], {%1, %2, %3, %4};"
                    :: "l"(out + (uint32_t)o1 * 64u + col),
                       "f"(acc[rt][2*p][2]), "f"(acc[rt][2*p][3]),
                       "f"(acc[rt][2*p+1][2]), "f"(acc[rt][2*p+1][3]) : "memory");
            }
        }
    }
}

// per-channel sum / sumsq (float4, proven 16-lane layout, 2 rows per iter),
// fused finalize (last block). Data is W-scaled; EPS compensated by WSC2.
__global__ __launch_bounds__(256)
void stats_kernel(const float* __restrict__ x, int N, float* __restrict__ sums,
                  const float* __restrict__ gamma, const float* __restrict__ beta,
                  float invN, float* __restrict__ sb, int cidx)
{
    const int t  = threadIdx.x;
    const int cg = t & 15;        // channel group (4 channels)
    const int rg = t >> 4;        // 16 row lanes per block
    float s0 = 0.f, s1 = 0.f, s2 = 0.f, s3 = 0.f;
    float q0 = 0.f, q1 = 0.f, q2 = 0.f, q3 = 0.f;
    const int stride = gridDim.x * 32;
    for (int r = blockIdx.x * 32 + rg; r < N; r += stride) {
        const float4 v = reinterpret_cast<const float4*>(x + (size_t)r * 64 + cg * 4)[0];
        s0 += v.x; s1 += v.y; s2 += v.z; s3 += v.w;
        q0 += v.x * v.x; q1 += v.y * v.y; q2 += v.z * v.z; q3 += v.w * v.w;
        const int r2 = r + 16;
        if (r2 < N) {
            const float4 u = reinterpret_cast<const float4*>(x + (size_t)r2 * 64 + cg * 4)[0];
            s0 += u.x; s1 += u.y; s2 += u.z; s3 += u.w;
            q0 += u.x * u.x; q1 += u.y * u.y; q2 += u.z * u.z; q3 += u.w * u.w;
        }
    }
    __shared__ float sh[256 * 8];
    __shared__ int last;
    float* my = sh + t * 8;
    my[0] = s0; my[1] = s1; my[2] = s2; my[3] = s3;
    my[4] = q0; my[5] = q1; my[6] = q2; my[7] = q3;
    __syncthreads();
    if (t < 64) {
        const int cgi = t >> 2;
        const int j   = t & 3;
        float S = 0.f, Q = 0.f;
        #pragma unroll
        for (int r = 0; r < 16; ++r) {
            const float* p = sh + (r * 16 + cgi) * 8 + j;
            S += p[0];
            Q += p[4];
        }
        atomicAdd(&sums[t],      S);
        atomicAdd(&sums[64 + t], Q);
    }
    // last block finalizes scale/shift
    __syncthreads();
    if (t == 0) {
        __threadfence();
        last = (atomicAdd(&g_cnt[cidx], 1u) == gridDim.x - 1) ? 1 : 0;
    }
    __syncthreads();
    if (last && t < 64) {
        const float mean = sums[t] * invN;
        const float var  = fmaxf(sums[64 + t] * invN - mean * mean, 0.f);
        const float s    = gamma[t] * rsqrtf(var + EPSV * WSC2);
        sb[t]      = s;
        sb[64 + t] = beta[t] - mean * s;
    }
}

__global__ __launch_bounds__(256)
void final_kernel(const float* __restrict__ conv2, const float* __restrict__ sb2,
                  const float* __restrict__ feat, float* __restrict__ out, int n4)
{
    int i = blockIdx.x * blockDim.x + threadIdx.x;
    for (int j = i; j < n4; j += gridDim.x * blockDim.x) {
        const float4 v = reinterpret_cast<const float4*>(conv2)[j];
        const float4 f = reinterpret_cast<const float4*>(feat)[j];
        const int c0 = (j & 15) * 4;
        float4 r;
        r.x = fmaxf(fmaf(v.x, sb2[c0 + 0], sb2[64 + c0 + 0]) + f.x, 0.f);
        r.y = fmaxf(fmaf(v.y, sb2[c0 + 1], sb2[64 + c0 + 1]) + f.y, 0.f);
        r.z = fmaxf(fmaf(v.z, sb2[c0 + 2], sb2[64 + c0 + 2]) + f.z, 0.f);
        r.w = fmaxf(fmaf(v.w, sb2[c0 + 3], sb2[64 + c0 + 3]) + f.w, 0.f);
        reinterpret_cast<float4*>(out)[j] = r;
    }
}

// ================= launcher =================
extern "C" void kernel_launch(void* const* d_in, const int* in_sizes, int n_in,
                              void* d_out, int out_size)
{
    const float* features = (const float*)d_in[0];
    const float* W1       = (const float*)d_in[1];
    const float* gamma1   = (const float*)d_in[2];
    const float* beta1    = (const float*)d_in[3];
    const float* W2       = (const float*)d_in[4];
    const float* gamma2   = (const float*)d_in[5];
    const float* beta2    = (const float*)d_in[6];
    const int*   in_maps  = (const int*)d_in[7];
    const int*   out_maps = (const int*)d_in[8];
    float*       out      = (float*)d_out;

    const int N = in_sizes[0] / CH;
    const int K = in_sizes[1] / (CH * CH);
    const int M = in_sizes[7] / K;

    float* buf1;  cudaGetSymbolAddress((void**)&buf1,  g_buf1);
    float* buf2;  cudaGetSymbolAddress((void**)&buf2,  g_buf2);
    float* stats; cudaGetSymbolAddress((void**)&stats, g_stats);
    float* sb;    cudaGetSymbolAddress((void**)&sb,    g_sb);
    __half* f;
    cudaGetSymbolAddress((void**)&f, g_f);
    uint2 *wf1, *wf2;
    cudaGetSymbolAddress((void**)&wf1, g_Wf1);
    cudaGetSymbolAddress((void**)&wf2, g_Wf2);

    cudaFuncSetAttribute(conv_mma_kernel,
                         cudaFuncAttributeMaxDynamicSharedMemorySize, SMEM_BYTES);

    const int total4 = N * (CH / 4);
    const float invN = 1.0f / (float)N;
    const dim3 convGrid((M + 127) / 128, K);
    const int pfBlocks = (N * 8 + 255) / 256;

    prep_w_kernel<<<dim3(K, 2), 256>>>(W1, W2, K);

    // conv1 (prep also zeroes buf1/buf2)
    prep_feat_kernel<<<pfBlocks, 256>>>(features, nullptr, buf1, buf2, N);
    conv_mma_kernel<<<convGrid, 256, SMEM_BYTES>>>(f, wf1,
                                                   in_maps, out_maps, buf1, M);
    stats_kernel<<<512, 256>>>(buf1, N, stats, gamma1, beta1, invN, sb, 0);

    // conv2 (BN1+ReLU fused into fp16 convert)
    prep_feat_kernel<<<pfBlocks, 256>>>(buf1, sb, nullptr, nullptr, N);
    conv_mma_kernel<<<convGrid, 256, SMEM_BYTES>>>(f, wf2,
                                                   in_maps, out_maps, buf2, M);
    stats_kernel<<<512, 256>>>(buf2, N, stats + 128, gamma2, beta2, invN,
                               sb + 128, 1);

    final_kernel<<<1024, 256>>>(buf2, sb + 128, features, out, total4);
}